// round 15
// baseline (speedup 1.0000x reference)
#include <cuda_runtime.h>
#include <cuda_bf16.h>
#include <cstdint>

// ---------------------------------------------------------------------------
// GNN_37082747634058: 3-layer GraphSAGE(mean) forward.
// == R14 champion (397.5us) + tapered layer-0 chunks + N-split gemm1 ==
// Layer-0 CSR on main stream -> 8-chunk (7x132+1x44 tiles) agg/gemm pipeline
// (agg on main, gemm on s2). prep_all + layers-1/2 CSR on s2 hidden under
// layer-0. Layers 1/2 serial; gemm1 launched as dim3(88,2) N=128 halves to
// fill the chip (88 CTAs < 148 SMs underfilled a wave).
// GEMMs: mma.sync m16n8k16 bf16 3-term split, ldmatrix.x4, 3-stage cp.async.
// Rules learned: (R8/R11) gather needs its own high-occupancy launch;
// (R12/R13) cross-stream chunk pipelines only for multi-wave chunks.
// ---------------------------------------------------------------------------

#define N0 1363968
#define N1 123904
#define N2 11264
#define N3 1024
#define E0 1239040
#define E1 112640
#define E2 10240
#define D_IN 128
#define D_H  256
#define D_OUT 64

#define EPB 4096
#define NB0 ((N1 + EPB - 1) / EPB)     // 31

#define L0_CHUNKS 8

// ------------------------- static device scratch ---------------------------
__device__ float g_mean0[(size_t)N1 * D_IN];
__device__ float g_h0   [(size_t)N1 * D_H];
__device__ float g_mean1[(size_t)N2 * D_H];
__device__ float g_h1   [(size_t)N2 * D_H];
__device__ float g_mean2[(size_t)N3 * D_H];

__device__ __nv_bfloat16 g_wt0h[256 * 256], g_wt0l[256 * 256];
__device__ __nv_bfloat16 g_wt1h[256 * 512], g_wt1l[256 * 512];
__device__ __nv_bfloat16 g_wt2h[64 * 512],  g_wt2l[64 * 512];

__device__ int g_cnt0[N1], g_off0[N1 + 1], g_cur0[N1], g_esrc0[E0];
__device__ int g_cnt1[N2], g_off1[N2 + 1], g_cur1[N2], g_esrc1[E1];
__device__ int g_cnt2[N3], g_off2[N3 + 1], g_cur2[N3], g_esrc2[E2];
__device__ int g_bsum[NB0 + 1];

// ------------------------------ helpers ------------------------------------
__device__ __forceinline__ void mma_bf16(float (&c)[4], const uint32_t (&a)[4],
                                         const uint32_t (&b)[2]) {
    asm volatile(
        "mma.sync.aligned.m16n8k16.row.col.f32.bf16.bf16.f32 "
        "{%0,%1,%2,%3}, {%4,%5,%6,%7}, {%8,%9}, {%0,%1,%2,%3};"
        : "+f"(c[0]), "+f"(c[1]), "+f"(c[2]), "+f"(c[3])
        : "r"(a[0]), "r"(a[1]), "r"(a[2]), "r"(a[3]), "r"(b[0]), "r"(b[1]));
}

__device__ __forceinline__ void ldmatrix_x4(uint32_t& r0, uint32_t& r1,
                                            uint32_t& r2, uint32_t& r3,
                                            uint32_t addr) {
    asm volatile("ldmatrix.sync.aligned.m8n8.x4.shared.b16 {%0,%1,%2,%3}, [%4];"
                 : "=r"(r0), "=r"(r1), "=r"(r2), "=r"(r3) : "r"(addr));
}

__device__ __forceinline__ void split_bf16(float2 f, uint32_t& hi, uint32_t& lo) {
    __nv_bfloat162 h2 = __float22bfloat162_rn(f);
    hi = *reinterpret_cast<uint32_t*>(&h2);
    float2 hf = __bfloat1622float2(h2);
    __nv_bfloat162 l2 = __float22bfloat162_rn(make_float2(f.x - hf.x, f.y - hf.y));
    lo = *reinterpret_cast<uint32_t*>(&l2);
}

__device__ __forceinline__ void cp_async16(void* smem_dst, const void* gmem_src) {
    uint32_t s = (uint32_t)__cvta_generic_to_shared(smem_dst);
    asm volatile("cp.async.cg.shared.global [%0], [%1], 16;\n"
                 :: "r"(s), "l"(gmem_src));
}
__device__ __forceinline__ void cp_async_commit() {
    asm volatile("cp.async.commit_group;\n" ::: "memory");
}
template <int NWait>
__device__ __forceinline__ void cp_async_wait() {
    asm volatile("cp.async.wait_group %0;\n" :: "n"(NWait) : "memory");
}

// ------------------------------ CSR build ----------------------------------
__global__ void zero0_kernel(int* c0) {
    int i = blockIdx.x * blockDim.x + threadIdx.x;
    if (i < N1) c0[i] = 0;
}
__global__ void zero12_kernel(int* c1, int* c2) {
    int i = blockIdx.x * blockDim.x + threadIdx.x;
    if (i < N2) c1[i] = 0;
    else if (i < N2 + N3) c2[i - N2] = 0;
}
__global__ void hist_kernel(const int* __restrict__ dst, int e, int* __restrict__ cnt) {
    int i = blockIdx.x * blockDim.x + threadIdx.x;
    if (i < e) atomicAdd(&cnt[dst[i]], 1);
}

__global__ void scanA_kernel(const int* __restrict__ cnt, int n, int* bsum) {
    __shared__ int wsum[32];
    const int t = threadIdx.x, lane = t & 31, w = t >> 5;
    const int base = blockIdx.x * EPB + t * 4;
    int s = 0;
#pragma unroll
    for (int i = 0; i < 4; i++) {
        int idx = base + i;
        if (idx < n) s += cnt[idx];
    }
#pragma unroll
    for (int d = 16; d > 0; d >>= 1) s += __shfl_down_sync(0xffffffffu, s, d);
    if (lane == 0) wsum[w] = s;
    __syncthreads();
    if (w == 0) {
        int v = wsum[lane];
#pragma unroll
        for (int d = 16; d > 0; d >>= 1) v += __shfl_down_sync(0xffffffffu, v, d);
        if (lane == 0) bsum[blockIdx.x] = v;
    }
}

// scanC with inline prefix of block sums (scanB merged).
__global__ void scanC_kernel(const int* __restrict__ cnt, int n, int total,
                             const int* __restrict__ bsum,
                             int* __restrict__ off, int* __restrict__ cur) {
    __shared__ int wsum[32];
    __shared__ int bpre_sh;
    const int t = threadIdx.x, lane = t & 31, w = t >> 5;
    if (t < 32) {
        int v = (lane < (int)blockIdx.x) ? bsum[lane] : 0;
#pragma unroll
        for (int d = 16; d > 0; d >>= 1) v += __shfl_down_sync(0xffffffffu, v, d);
        if (lane == 0) bpre_sh = v;
    }
    const int base = blockIdx.x * EPB + t * 4;
    int v[4];
#pragma unroll
    for (int i = 0; i < 4; i++) {
        int idx = base + i;
        v[i] = (idx < n) ? cnt[idx] : 0;
    }
    int s = v[0] + v[1] + v[2] + v[3];
    int incl = s;
#pragma unroll
    for (int d = 1; d < 32; d <<= 1) {
        int o = __shfl_up_sync(0xffffffffu, incl, d);
        if (lane >= d) incl += o;
    }
    if (lane == 31) wsum[w] = incl;
    __syncthreads();
    if (w == 0) {
        int x = wsum[lane];
        int xi = x;
#pragma unroll
        for (int d = 1; d < 32; d <<= 1) {
            int o = __shfl_up_sync(0xffffffffu, xi, d);
            if (lane >= d) xi += o;
        }
        wsum[lane] = xi - x;
    }
    __syncthreads();
    int run = bpre_sh + wsum[w] + (incl - s);
#pragma unroll
    for (int i = 0; i < 4; i++) {
        int idx = base + i;
        if (idx < n) { off[idx] = run; cur[idx] = run; }
        run += v[i];
    }
    if (blockIdx.x == 0 && t == 0) off[n] = total;
}

__device__ void exscan_block(const int* __restrict__ cnt, int n,
                             int* __restrict__ off, int* __restrict__ cur,
                             int total) {
    __shared__ int wsum[32];
    __shared__ int carry_sh;
    __shared__ int tot_sh;
    const int t = threadIdx.x, lane = t & 31, w = t >> 5;
    if (t == 0) carry_sh = 0;
    __syncthreads();
    for (int base = 0; base < n; base += 4096) {
        int idx = base + t * 4;
        int v[4];
#pragma unroll
        for (int i = 0; i < 4; i++) v[i] = (idx + i < n) ? cnt[idx + i] : 0;
        int s = v[0] + v[1] + v[2] + v[3];
        int incl = s;
#pragma unroll
        for (int d = 1; d < 32; d <<= 1) {
            int o = __shfl_up_sync(0xffffffffu, incl, d);
            if (lane >= d) incl += o;
        }
        if (lane == 31) wsum[w] = incl;
        __syncthreads();
        if (w == 0) {
            int x = wsum[lane];
            int xi = x;
#pragma unroll
            for (int d = 1; d < 32; d <<= 1) {
                int o = __shfl_up_sync(0xffffffffu, xi, d);
                if (lane >= d) xi += o;
            }
            if (lane == 31) tot_sh = xi;
            wsum[lane] = xi - x;
        }
        __syncthreads();
        int run = carry_sh + wsum[w] + (incl - s);
#pragma unroll
        for (int i = 0; i < 4; i++) {
            if (idx + i < n) { off[idx + i] = run; cur[idx + i] = run; }
            run += v[i];
        }
        __syncthreads();
        if (t == 0) carry_sh += tot_sh;
        __syncthreads();
    }
    if (t == 0) off[n] = total;
}
__global__ void exscan12_kernel(const int* c1, int* o1, int* u1,
                                const int* c2, int* o2, int* u2) {
    if (blockIdx.x == 0) exscan_block(c1, N2, o1, u1, E1);
    else exscan_block(c2, N3, o2, u2, E2);
}

__global__ void scatter_kernel(const int* __restrict__ src, const int* __restrict__ dst,
                               int e, int* __restrict__ cur, int* __restrict__ esrc) {
    int i = blockIdx.x * blockDim.x + threadIdx.x;
    if (i < e) {
        int p = atomicAdd(&cur[dst[i]], 1);
        esrc[p] = src[i];
    }
}
__global__ void scatter12_kernel(const int* s1, const int* d1, int* u1, int* e1,
                                 const int* s2, const int* d2, int* u2, int* e2) {
    int i = blockIdx.x * blockDim.x + threadIdx.x;
    if (i < E1) {
        int p = atomicAdd(&u1[d1[i]], 1); e1[p] = s1[i];
    } else if (i < E1 + E2) {
        int j = i - E1;
        int p = atomicAdd(&u2[d2[j]], 1); e2[p] = s2[j];
    }
}

// ------------------------- warp-per-dst mean aggregation -------------------
template <int D>
__global__ void aggregate_kernel(const float* __restrict__ X,
                                 const int* __restrict__ off,
                                 const int* __restrict__ srcs,
                                 float* __restrict__ out, int n_dst, int dstBase) {
    int g = (blockIdx.x * blockDim.x + threadIdx.x) >> 5;
    if (g >= n_dst) return;
    g += dstBase;
    int lane = threadIdx.x & 31;
    int beg = off[g], end = off[g + 1];
    float4 a0 = make_float4(0.f, 0.f, 0.f, 0.f);
    float4 a1 = make_float4(0.f, 0.f, 0.f, 0.f);
    int j = beg;
    for (; j + 3 < end; j += 4) {
        int s0 = srcs[j], s1 = srcs[j + 1], s2 = srcs[j + 2], s3 = srcs[j + 3];
        const float4* r0 = (const float4*)(X + (size_t)s0 * D);
        const float4* r1 = (const float4*)(X + (size_t)s1 * D);
        const float4* r2 = (const float4*)(X + (size_t)s2 * D);
        const float4* r3 = (const float4*)(X + (size_t)s3 * D);
        float4 v0 = r0[lane], v1 = r1[lane], v2 = r2[lane], v3 = r3[lane];
        a0.x += (v0.x + v1.x) + (v2.x + v3.x);
        a0.y += (v0.y + v1.y) + (v2.y + v3.y);
        a0.z += (v0.z + v1.z) + (v2.z + v3.z);
        a0.w += (v0.w + v1.w) + (v2.w + v3.w);
        if (D == 256) {
            float4 u0 = r0[lane + 32], u1 = r1[lane + 32];
            float4 u2 = r2[lane + 32], u3 = r3[lane + 32];
            a1.x += (u0.x + u1.x) + (u2.x + u3.x);
            a1.y += (u0.y + u1.y) + (u2.y + u3.y);
            a1.z += (u0.z + u1.z) + (u2.z + u3.z);
            a1.w += (u0.w + u1.w) + (u2.w + u3.w);
        }
    }
    for (; j < end; j++) {
        int s = srcs[j];
        const float4* row = (const float4*)(X + (size_t)s * D);
        float4 v = row[lane];
        a0.x += v.x; a0.y += v.y; a0.z += v.z; a0.w += v.w;
        if (D == 256) {
            float4 u = row[lane + 32];
            a1.x += u.x; a1.y += u.y; a1.z += u.z; a1.w += u.w;
        }
    }
    int c = end - beg;
    float inv = 1.0f / (float)(c > 0 ? c : 1);
    float4* o = (float4*)(out + (size_t)g * D);
    o[lane] = make_float4(a0.x * inv, a0.y * inv, a0.z * inv, a0.w * inv);
    if (D == 256)
        o[lane + 32] = make_float4(a1.x * inv, a1.y * inv, a1.z * inv, a1.w * inv);
}

// ---------------- weight transpose + bf16 hi/lo split ----------------------
__device__ __forceinline__ void prep_one(const float* Wl, const float* Wr,
                                         int K1, int K, int N, int idx,
                                         __nv_bfloat16* hi, __nv_bfloat16* lo) {
    int n = idx / K, k = idx % K;
    float v = (k < K1) ? Wl[(size_t)k * N + n] : Wr[(size_t)(k - K1) * N + n];
    __nv_bfloat16 h = __float2bfloat16_rn(v);
    hi[(size_t)n * K + k] = h;
    lo[(size_t)n * K + k] = __float2bfloat16_rn(v - __bfloat162float(h));
}

__global__ void prep_all_kernel(const float* Wl0, const float* Wr0,
                                const float* Wl1, const float* Wr1,
                                const float* Wl2, const float* Wr2,
                                __nv_bfloat16* h0, __nv_bfloat16* l0,
                                __nv_bfloat16* h1, __nv_bfloat16* l1,
                                __nv_bfloat16* h2, __nv_bfloat16* l2) {
    int i = blockIdx.x * blockDim.x + threadIdx.x;
    const int S0 = 256 * 256, S1 = 256 * 512, S2 = 64 * 512;
    if (i < S0) prep_one(Wl0, Wr0, D_IN, 2 * D_IN, D_H, i, h0, l0);
    else if (i < S0 + S1) prep_one(Wl1, Wr1, D_H, 2 * D_H, D_H, i - S0, h1, l1);
    else if (i < S0 + S1 + S2) prep_one(Wl2, Wr2, D_H, 2 * D_H, D_OUT, i - S0 - S1, h2, l2);
}

// ----------------------- bf16x3 mma.sync SAGE GEMM -------------------------
// gridDim.y selects an N-wide column slab (blockIdx.y * N); ldC is the
// output row stride (equals total N of the layer).
template <int N, bool RELU>
__global__ void __launch_bounds__(256, 1)
sage_mma_gemm(const float* __restrict__ Aagg, int K1,
              const float* __restrict__ Adst, int ldDst, int K,
              const __nv_bfloat16* __restrict__ Wth,
              const __nv_bfloat16* __restrict__ Wtl,
              const float* __restrict__ bias, float* __restrict__ C,
              int rowOff, int ldC) {
    extern __shared__ char smem[];
    constexpr int ASTR = 36;
    constexpr int BSTR = 40;
    constexpr int ABYTES = 128 * ASTR * 4;
    constexpr int BBYTES = N * BSTR * 2;
    constexpr int STAGE = ABYTES + 2 * BBYTES;
    const int tid = threadIdx.x;
    const int wid = tid >> 5;
    const int lane = tid & 31;
    const int g = lane >> 2;
    const int t = lane & 3;
    const int wm = (wid & 3) * 32;
    const int wn = (wid >> 2) * (N / 2);
    const int rowBase = rowOff + blockIdx.x * 128;
    const int NC = K / 32;
    constexpr int NIN = N / 16;

    // column-slab offset (gemm1 N-split): shift weights/bias/output pointers
    const int colBase = blockIdx.y * N;
    Wth += (size_t)colBase * K;
    Wtl += (size_t)colBase * K;
    bias += colBase;
    C += colBase;

    const int q = lane >> 3;
    const uint32_t bLaneOff =
        (uint32_t)((wn + ((q & 2) << 2) + (lane & 7)) * (BSTR * 2) + (q & 1) * 16);

    float acc[2][NIN][4];
#pragma unroll
    for (int im = 0; im < 2; im++)
#pragma unroll
        for (int i = 0; i < NIN; i++)
#pragma unroll
            for (int qq = 0; qq < 4; qq++) acc[im][i][qq] = 0.f;

    auto issue_chunk = [&](int kc, int b) {
        char* stage = smem + b * STAGE;
        float* As = (float*)stage;
        __nv_bfloat16* Bh = (__nv_bfloat16*)(stage + ABYTES);
        __nv_bfloat16* Bl = (__nv_bfloat16*)(stage + ABYTES + BBYTES);
        const int acol = kc * 32;
        const bool inAgg = acol < K1;
        const float* abase = inAgg ? (Aagg + acol) : (Adst + (acol - K1));
        const int ald = inAgg ? K1 : ldDst;
#pragma unroll
        for (int p = 0; p < 4; p++) {
            int idx = p * 256 + tid;
            int r = idx >> 3, c4 = idx & 7;
            cp_async16(&As[r * ASTR + c4 * 4],
                       abase + (size_t)(rowBase + r) * ald + c4 * 4);
        }
#pragma unroll
        for (int p = 0; p < N / 64; p++) {
            int idx = p * 256 + tid;
            int r = idx >> 2, c8 = idx & 3;
            cp_async16(&Bh[r * BSTR + c8 * 8], Wth + (size_t)r * K + acol + c8 * 8);
            cp_async16(&Bl[r * BSTR + c8 * 8], Wtl + (size_t)r * K + acol + c8 * 8);
        }
        cp_async_commit();
    };

    issue_chunk(0, 0);
    if (NC > 1) issue_chunk(1, 1);

    for (int kc = 0; kc < NC; kc++) {
        const int b = kc % 3;
        __syncthreads();
        if (kc + 2 < NC) {
            issue_chunk(kc + 2, (kc + 2) % 3);
            cp_async_wait<2>();
        } else if (kc + 1 < NC) {
            cp_async_wait<1>();
        } else {
            cp_async_wait<0>();
        }
        __syncthreads();

        char* stage = smem + b * STAGE;
        const float* Ab = (const float*)stage;
        const uint32_t bhAddr =
            (uint32_t)__cvta_generic_to_shared(stage + ABYTES) + bLaneOff;
        const uint32_t blAddr = bhAddr + BBYTES;
#pragma unroll
        for (int s = 0; s < 2; s++) {
            const int kb = s * 16;
            uint32_t ah[2][4], al[2][4];
#pragma unroll
            for (int im = 0; im < 2; im++) {
                const int r0 = wm + im * 16 + g;
                float2 f0 = *(const float2*)&Ab[r0 * ASTR + kb + 2 * t];
                float2 f1 = *(const float2*)&Ab[(r0 + 8) * ASTR + kb + 2 * t];
                float2 f2 = *(const float2*)&Ab[r0 * ASTR + kb + 8 + 2 * t];
                float2 f3 = *(const float2*)&Ab[(r0 + 8) * ASTR + kb + 8 + 2 * t];
                split_bf16(f0, ah[im][0], al[im][0]);
                split_bf16(f1, ah[im][1], al[im][1]);
                split_bf16(f2, ah[im][2], al[im][2]);
                split_bf16(f3, ah[im][3], al[im][3]);
            }
#pragma unroll
            for (int i2 = 0; i2 < NIN / 2; i2++) {
                const uint32_t off = (uint32_t)(i2 * 16 * (BSTR * 2) + kb * 2);
                uint32_t bh[4], bl[4];
                ldmatrix_x4(bh[0], bh[1], bh[2], bh[3], bhAddr + off);
                ldmatrix_x4(bl[0], bl[1], bl[2], bl[3], blAddr + off);
                const uint32_t h0[2] = {bh[0], bh[1]};
                const uint32_t h1[2] = {bh[2], bh[3]};
                const uint32_t l0[2] = {bl[0], bl[1]};
                const uint32_t l1[2] = {bl[2], bl[3]};
                mma_bf16(acc[0][2 * i2], ah[0], h0);
                mma_bf16(acc[1][2 * i2], ah[1], h0);
                mma_bf16(acc[0][2 * i2], ah[0], l0);
                mma_bf16(acc[1][2 * i2], ah[1], l0);
                mma_bf16(acc[0][2 * i2], al[0], h0);
                mma_bf16(acc[1][2 * i2], al[1], h0);
                mma_bf16(acc[0][2 * i2 + 1], ah[0], h1);
                mma_bf16(acc[1][2 * i2 + 1], ah[1], h1);
                mma_bf16(acc[0][2 * i2 + 1], ah[0], l1);
                mma_bf16(acc[1][2 * i2 + 1], ah[1], l1);
                mma_bf16(acc[0][2 * i2 + 1], al[0], h1);
                mma_bf16(acc[1][2 * i2 + 1], al[1], h1);
            }
        }
    }

    // ---- epilogue ----
#pragma unroll
    for (int i = 0; i < NIN; i++) {
        const int col = wn + i * 8 + 2 * t;
        const float b0 = __ldg(bias + col);
        const float b1 = __ldg(bias + col + 1);
#pragma unroll
        for (int im = 0; im < 2; im++) {
            const int row = rowBase + wm + im * 16 + g;
            float v0 = acc[im][i][0] + b0;
            float v1 = acc[im][i][1] + b1;
            float v2 = acc[im][i][2] + b0;
            float v3 = acc[im][i][3] + b1;
            if (RELU) {
                v0 = fmaxf(v0, 0.f); v1 = fmaxf(v1, 0.f);
                v2 = fmaxf(v2, 0.f); v3 = fmaxf(v3, 0.f);
            }
            *(float2*)&C[(size_t)row * ldC + col] = make_float2(v0, v1);
            *(float2*)&C[(size_t)(row + 8) * ldC + col] = make_float2(v2, v3);
        }
    }
}

// ------------------------------- launcher ----------------------------------
static inline int cdiv(int a, int b) { return (a + b - 1) / b; }

extern "C" void kernel_launch(void* const* d_in, const int* in_sizes, int n_in,
                              void* d_out, int out_size) {
    const float* x   = (const float*)d_in[0];
    const float* Wl0 = (const float*)d_in[1];
    const float* bl0 = (const float*)d_in[2];
    const float* Wr0 = (const float*)d_in[3];
    const float* Wl1 = (const float*)d_in[4];
    const float* bl1 = (const float*)d_in[5];
    const float* Wr1 = (const float*)d_in[6];
    const float* Wl2 = (const float*)d_in[7];
    const float* bl2 = (const float*)d_in[8];
    const float* Wr2 = (const float*)d_in[9];
    const int* es0 = (const int*)d_in[10];
    const int* ed0 = (const int*)d_in[11];
    const int* es1 = (const int*)d_in[12];
    const int* ed1 = (const int*)d_in[13];
    const int* es2 = (const int*)d_in[14];
    const int* ed2 = (const int*)d_in[15];
    float* out = (float*)d_out;

    float *mean0, *h0, *mean1, *h1, *mean2;
    __nv_bfloat16 *wt0h, *wt0l, *wt1h, *wt1l, *wt2h, *wt2l;
    int *cnt0, *off0, *cur0, *esrc0;
    int *cnt1, *off1, *cur1, *esrc1;
    int *cnt2, *off2, *cur2, *esrc2;
    int *bsum;
    cudaGetSymbolAddress((void**)&mean0, g_mean0);
    cudaGetSymbolAddress((void**)&h0, g_h0);
    cudaGetSymbolAddress((void**)&mean1, g_mean1);
    cudaGetSymbolAddress((void**)&h1, g_h1);
    cudaGetSymbolAddress((void**)&mean2, g_mean2);
    cudaGetSymbolAddress((void**)&wt0h, g_wt0h);
    cudaGetSymbolAddress((void**)&wt0l, g_wt0l);
    cudaGetSymbolAddress((void**)&wt1h, g_wt1h);
    cudaGetSymbolAddress((void**)&wt1l, g_wt1l);
    cudaGetSymbolAddress((void**)&wt2h, g_wt2h);
    cudaGetSymbolAddress((void**)&wt2l, g_wt2l);
    cudaGetSymbolAddress((void**)&cnt0, g_cnt0);
    cudaGetSymbolAddress((void**)&off0, g_off0);
    cudaGetSymbolAddress((void**)&cur0, g_cur0);
    cudaGetSymbolAddress((void**)&esrc0, g_esrc0);
    cudaGetSymbolAddress((void**)&cnt1, g_cnt1);
    cudaGetSymbolAddress((void**)&off1, g_off1);
    cudaGetSymbolAddress((void**)&cur1, g_cur1);
    cudaGetSymbolAddress((void**)&esrc1, g_esrc1);
    cudaGetSymbolAddress((void**)&cnt2, g_cnt2);
    cudaGetSymbolAddress((void**)&off2, g_off2);
    cudaGetSymbolAddress((void**)&cur2, g_cur2);
    cudaGetSymbolAddress((void**)&esrc2, g_esrc2);
    cudaGetSymbolAddress((void**)&bsum, g_bsum);

    static cudaStream_t s2 = nullptr;
    static cudaEvent_t evStart, evA[L0_CHUNKS], evG, evCSR12;
    if (!s2) {
        cudaStreamCreateWithFlags(&s2, cudaStreamNonBlocking);
        cudaEventCreateWithFlags(&evStart, cudaEventDisableTiming);
        for (int i = 0; i < L0_CHUNKS; i++)
            cudaEventCreateWithFlags(&evA[i], cudaEventDisableTiming);
        cudaEventCreateWithFlags(&evG, cudaEventDisableTiming);
        cudaEventCreateWithFlags(&evCSR12, cudaEventDisableTiming);
    }

    constexpr int SMEM_256 = 3 * (128 * 36 * 4 + 2 * 256 * 40 * 2);  // 178176
    constexpr int SMEM_128 = 3 * (128 * 36 * 4 + 2 * 128 * 40 * 2);  // 116736
    constexpr int SMEM_64  = 3 * (128 * 36 * 4 + 2 * 64 * 40 * 2);   // 86016
    cudaFuncSetAttribute(sage_mma_gemm<256, true>,
                         cudaFuncAttributeMaxDynamicSharedMemorySize, SMEM_256);
    cudaFuncSetAttribute(sage_mma_gemm<128, false>,
                         cudaFuncAttributeMaxDynamicSharedMemorySize, SMEM_128);
    cudaFuncSetAttribute(sage_mma_gemm<64, true>,
                         cudaFuncAttributeMaxDynamicSharedMemorySize, SMEM_64);

    // fork s2 from the capturing (main) stream
    cudaEventRecord(evStart, 0);
    cudaStreamWaitEvent(s2, evStart, 0);

    // ---- s2: weight prep + layers 1/2 CSR build (hidden under layer 0) ----
    prep_all_kernel<<<cdiv(256 * 256 + 256 * 512 + 64 * 512, 256), 256, 0, s2>>>(
        Wl0, Wr0, Wl1, Wr1, Wl2, Wr2, wt0h, wt0l, wt1h, wt1l, wt2h, wt2l);
    zero12_kernel<<<cdiv(N2 + N3, 256), 256, 0, s2>>>(cnt1, cnt2);
    hist_kernel<<<cdiv(E1, 256), 256, 0, s2>>>(ed1, E1, cnt1);
    hist_kernel<<<cdiv(E2, 256), 256, 0, s2>>>(ed2, E2, cnt2);
    exscan12_kernel<<<2, 1024, 0, s2>>>(cnt1, off1, cur1, cnt2, off2, cur2);
    scatter12_kernel<<<cdiv(E1 + E2, 256), 256, 0, s2>>>(
        es1, ed1, cur1, esrc1, es2, ed2, cur2, esrc2);
    cudaEventRecord(evCSR12, s2);

    // ---- main: layer-0 CSR build (scanB merged into scanC) ----
    zero0_kernel<<<cdiv(N1, 256), 256>>>(cnt0);
    hist_kernel<<<cdiv(E0, 256), 256>>>(ed0, E0, cnt0);
    scanA_kernel<<<NB0, 1024>>>(cnt0, N1, bsum);
    scanC_kernel<<<NB0, 1024>>>(cnt0, N1, E0, bsum, off0, cur0);
    scatter_kernel<<<cdiv(E0, 256), 256>>>(es0, ed0, E0, cur0, esrc0);

    // ---- layer 0: tapered 8-chunk agg (main) / gemm (s2) pipeline ----
    // 7x132 + 1x44 tiles: small final chunk minimizes the exposed gemm tail.
    static const int tileOff[L0_CHUNKS + 1] =
        {0, 132, 264, 396, 528, 660, 792, 924, 968};
    for (int c = 0; c < L0_CHUNKS; c++) {
        const int tiles = tileOff[c + 1] - tileOff[c];
        const int rows = tiles * 128;
        const int rowBase = tileOff[c] * 128;
        aggregate_kernel<128><<<tiles * 16, 256>>>(
            x, off0, esrc0, mean0, rows, rowBase);
        cudaEventRecord(evA[c], 0);
        cudaStreamWaitEvent(s2, evA[c], 0);
        sage_mma_gemm<256, true><<<tiles, 256, SMEM_256, s2>>>(
            mean0, D_IN, x, D_IN, 2 * D_IN, wt0h, wt0l, bl0, h0, rowBase, D_H);
    }
    cudaEventRecord(evG, s2);
    cudaStreamWaitEvent(0, evG, 0);
    cudaStreamWaitEvent(0, evCSR12, 0);

    // ---- layer 1 (serial; gemm N-split into 2 column slabs, one launch) ----
    aggregate_kernel<256><<<cdiv(N2 * 32, 256), 256>>>(h0, off1, esrc1, mean1, N2, 0);
    sage_mma_gemm<128, false><<<dim3(N2 / 128, 2), 256, SMEM_128>>>(
        mean1, D_H, h0, D_H, 2 * D_H, wt1h, wt1l, bl1, h1, 0, D_H);

    // ---- layer 2 (serial) ----
    aggregate_kernel<256><<<cdiv(N3 * 32, 256), 256>>>(h1, off2, esrc2, mean2, N3, 0);
    sage_mma_gemm<64, true><<<N3 / 128, 256, SMEM_64>>>(
        mean2, D_H, h1, D_H, 2 * D_H, wt2h, wt2l, bl2, out, 0, D_OUT);
}

// round 16
// speedup vs baseline: 1.0618x; 1.0618x over previous
#include <cuda_runtime.h>
#include <cuda_bf16.h>
#include <cstdint>

// ---------------------------------------------------------------------------
// GNN_37082747634058: 3-layer GraphSAGE(mean) forward.
// == R14 champion, verbatim (397.5us, reproduced twice) ==
// Layer-0 CSR on main stream -> 8-chunk agg/gemm pipeline (agg on main,
// gemm on side stream s2). prep_all + layers-1/2 CSR run on s2, hidden
// under layer-0. Layers 1/2 run serially. GEMMs: mma.sync m16n8k16 bf16
// 3-term split (hi*hi + hi*lo + lo*hi, fp32 accum), ldmatrix.x4 B fragments,
// 3-stage cp.async pipeline. scanB merged into scanC.
// Rules learned this session:
//  (R8/R11)  the DRAM-bound gather needs its own high-occupancy launch;
//            fusing it under a big-SMEM GEMM config loses 2x.
//  (R12/R13) cross-stream chunk pipelines only pay for multi-wave chunks;
//            layers 1/2 are too small.
//  (R15)     N-splitting gemm1 and tapered chunks both regress.
// ---------------------------------------------------------------------------

#define N0 1363968
#define N1 123904
#define N2 11264
#define N3 1024
#define E0 1239040
#define E1 112640
#define E2 10240
#define D_IN 128
#define D_H  256
#define D_OUT 64

#define EPB 4096
#define NB0 ((N1 + EPB - 1) / EPB)     // 31

#define L0_CHUNKS 8
#define L0_ROWS   (N1 / L0_CHUNKS)     // 15488
#define L0_TILES  (L0_ROWS / 128)      // 121

// ------------------------- static device scratch ---------------------------
__device__ float g_mean0[(size_t)N1 * D_IN];
__device__ float g_h0   [(size_t)N1 * D_H];
__device__ float g_mean1[(size_t)N2 * D_H];
__device__ float g_h1   [(size_t)N2 * D_H];
__device__ float g_mean2[(size_t)N3 * D_H];

__device__ __nv_bfloat16 g_wt0h[256 * 256], g_wt0l[256 * 256];
__device__ __nv_bfloat16 g_wt1h[256 * 512], g_wt1l[256 * 512];
__device__ __nv_bfloat16 g_wt2h[64 * 512],  g_wt2l[64 * 512];

__device__ int g_cnt0[N1], g_off0[N1 + 1], g_cur0[N1], g_esrc0[E0];
__device__ int g_cnt1[N2], g_off1[N2 + 1], g_cur1[N2], g_esrc1[E1];
__device__ int g_cnt2[N3], g_off2[N3 + 1], g_cur2[N3], g_esrc2[E2];
__device__ int g_bsum[NB0 + 1];

// ------------------------------ helpers ------------------------------------
__device__ __forceinline__ void mma_bf16(float (&c)[4], const uint32_t (&a)[4],
                                         const uint32_t (&b)[2]) {
    asm volatile(
        "mma.sync.aligned.m16n8k16.row.col.f32.bf16.bf16.f32 "
        "{%0,%1,%2,%3}, {%4,%5,%6,%7}, {%8,%9}, {%0,%1,%2,%3};"
        : "+f"(c[0]), "+f"(c[1]), "+f"(c[2]), "+f"(c[3])
        : "r"(a[0]), "r"(a[1]), "r"(a[2]), "r"(a[3]), "r"(b[0]), "r"(b[1]));
}

__device__ __forceinline__ void ldmatrix_x4(uint32_t& r0, uint32_t& r1,
                                            uint32_t& r2, uint32_t& r3,
                                            uint32_t addr) {
    asm volatile("ldmatrix.sync.aligned.m8n8.x4.shared.b16 {%0,%1,%2,%3}, [%4];"
                 : "=r"(r0), "=r"(r1), "=r"(r2), "=r"(r3) : "r"(addr));
}

__device__ __forceinline__ void split_bf16(float2 f, uint32_t& hi, uint32_t& lo) {
    __nv_bfloat162 h2 = __float22bfloat162_rn(f);
    hi = *reinterpret_cast<uint32_t*>(&h2);
    float2 hf = __bfloat1622float2(h2);
    __nv_bfloat162 l2 = __float22bfloat162_rn(make_float2(f.x - hf.x, f.y - hf.y));
    lo = *reinterpret_cast<uint32_t*>(&l2);
}

__device__ __forceinline__ void cp_async16(void* smem_dst, const void* gmem_src) {
    uint32_t s = (uint32_t)__cvta_generic_to_shared(smem_dst);
    asm volatile("cp.async.cg.shared.global [%0], [%1], 16;\n"
                 :: "r"(s), "l"(gmem_src));
}
__device__ __forceinline__ void cp_async_commit() {
    asm volatile("cp.async.commit_group;\n" ::: "memory");
}
template <int NWait>
__device__ __forceinline__ void cp_async_wait() {
    asm volatile("cp.async.wait_group %0;\n" :: "n"(NWait) : "memory");
}

// ------------------------------ CSR build ----------------------------------
__global__ void zero0_kernel(int* c0) {
    int i = blockIdx.x * blockDim.x + threadIdx.x;
    if (i < N1) c0[i] = 0;
}
__global__ void zero12_kernel(int* c1, int* c2) {
    int i = blockIdx.x * blockDim.x + threadIdx.x;
    if (i < N2) c1[i] = 0;
    else if (i < N2 + N3) c2[i - N2] = 0;
}
__global__ void hist_kernel(const int* __restrict__ dst, int e, int* __restrict__ cnt) {
    int i = blockIdx.x * blockDim.x + threadIdx.x;
    if (i < e) atomicAdd(&cnt[dst[i]], 1);
}

__global__ void scanA_kernel(const int* __restrict__ cnt, int n, int* bsum) {
    __shared__ int wsum[32];
    const int t = threadIdx.x, lane = t & 31, w = t >> 5;
    const int base = blockIdx.x * EPB + t * 4;
    int s = 0;
#pragma unroll
    for (int i = 0; i < 4; i++) {
        int idx = base + i;
        if (idx < n) s += cnt[idx];
    }
#pragma unroll
    for (int d = 16; d > 0; d >>= 1) s += __shfl_down_sync(0xffffffffu, s, d);
    if (lane == 0) wsum[w] = s;
    __syncthreads();
    if (w == 0) {
        int v = wsum[lane];
#pragma unroll
        for (int d = 16; d > 0; d >>= 1) v += __shfl_down_sync(0xffffffffu, v, d);
        if (lane == 0) bsum[blockIdx.x] = v;
    }
}

// scanC with inline prefix of block sums (scanB merged: each block reduces
// the bsum entries below it -- nb is tiny, 31 entries).
__global__ void scanC_kernel(const int* __restrict__ cnt, int n, int total,
                             const int* __restrict__ bsum,
                             int* __restrict__ off, int* __restrict__ cur) {
    __shared__ int wsum[32];
    __shared__ int bpre_sh;
    const int t = threadIdx.x, lane = t & 31, w = t >> 5;
    if (t < 32) {
        int v = (lane < (int)blockIdx.x) ? bsum[lane] : 0;
#pragma unroll
        for (int d = 16; d > 0; d >>= 1) v += __shfl_down_sync(0xffffffffu, v, d);
        if (lane == 0) bpre_sh = v;
    }
    const int base = blockIdx.x * EPB + t * 4;
    int v[4];
#pragma unroll
    for (int i = 0; i < 4; i++) {
        int idx = base + i;
        v[i] = (idx < n) ? cnt[idx] : 0;
    }
    int s = v[0] + v[1] + v[2] + v[3];
    int incl = s;
#pragma unroll
    for (int d = 1; d < 32; d <<= 1) {
        int o = __shfl_up_sync(0xffffffffu, incl, d);
        if (lane >= d) incl += o;
    }
    if (lane == 31) wsum[w] = incl;
    __syncthreads();
    if (w == 0) {
        int x = wsum[lane];
        int xi = x;
#pragma unroll
        for (int d = 1; d < 32; d <<= 1) {
            int o = __shfl_up_sync(0xffffffffu, xi, d);
            if (lane >= d) xi += o;
        }
        wsum[lane] = xi - x;
    }
    __syncthreads();
    int run = bpre_sh + wsum[w] + (incl - s);
#pragma unroll
    for (int i = 0; i < 4; i++) {
        int idx = base + i;
        if (idx < n) { off[idx] = run; cur[idx] = run; }
        run += v[i];
    }
    if (blockIdx.x == 0 && t == 0) off[n] = total;
}

__device__ void exscan_block(const int* __restrict__ cnt, int n,
                             int* __restrict__ off, int* __restrict__ cur,
                             int total) {
    __shared__ int wsum[32];
    __shared__ int carry_sh;
    __shared__ int tot_sh;
    const int t = threadIdx.x, lane = t & 31, w = t >> 5;
    if (t == 0) carry_sh = 0;
    __syncthreads();
    for (int base = 0; base < n; base += 4096) {
        int idx = base + t * 4;
        int v[4];
#pragma unroll
        for (int i = 0; i < 4; i++) v[i] = (idx + i < n) ? cnt[idx + i] : 0;
        int s = v[0] + v[1] + v[2] + v[3];
        int incl = s;
#pragma unroll
        for (int d = 1; d < 32; d <<= 1) {
            int o = __shfl_up_sync(0xffffffffu, incl, d);
            if (lane >= d) incl += o;
        }
        if (lane == 31) wsum[w] = incl;
        __syncthreads();
        if (w == 0) {
            int x = wsum[lane];
            int xi = x;
#pragma unroll
            for (int d = 1; d < 32; d <<= 1) {
                int o = __shfl_up_sync(0xffffffffu, xi, d);
                if (lane >= d) xi += o;
            }
            if (lane == 31) tot_sh = xi;
            wsum[lane] = xi - x;
        }
        __syncthreads();
        int run = carry_sh + wsum[w] + (incl - s);
#pragma unroll
        for (int i = 0; i < 4; i++) {
            if (idx + i < n) { off[idx + i] = run; cur[idx + i] = run; }
            run += v[i];
        }
        __syncthreads();
        if (t == 0) carry_sh += tot_sh;
        __syncthreads();
    }
    if (t == 0) off[n] = total;
}
__global__ void exscan12_kernel(const int* c1, int* o1, int* u1,
                                const int* c2, int* o2, int* u2) {
    if (blockIdx.x == 0) exscan_block(c1, N2, o1, u1, E1);
    else exscan_block(c2, N3, o2, u2, E2);
}

__global__ void scatter_kernel(const int* __restrict__ src, const int* __restrict__ dst,
                               int e, int* __restrict__ cur, int* __restrict__ esrc) {
    int i = blockIdx.x * blockDim.x + threadIdx.x;
    if (i < e) {
        int p = atomicAdd(&cur[dst[i]], 1);
        esrc[p] = src[i];
    }
}
__global__ void scatter12_kernel(const int* s1, const int* d1, int* u1, int* e1,
                                 const int* s2, const int* d2, int* u2, int* e2) {
    int i = blockIdx.x * blockDim.x + threadIdx.x;
    if (i < E1) {
        int p = atomicAdd(&u1[d1[i]], 1); e1[p] = s1[i];
    } else if (i < E1 + E2) {
        int j = i - E1;
        int p = atomicAdd(&u2[d2[j]], 1); e2[p] = s2[j];
    }
}

// ------------------------- warp-per-dst mean aggregation -------------------
template <int D>
__global__ void aggregate_kernel(const float* __restrict__ X,
                                 const int* __restrict__ off,
                                 const int* __restrict__ srcs,
                                 float* __restrict__ out, int n_dst, int dstBase) {
    int g = (blockIdx.x * blockDim.x + threadIdx.x) >> 5;
    if (g >= n_dst) return;
    g += dstBase;
    int lane = threadIdx.x & 31;
    int beg = off[g], end = off[g + 1];
    float4 a0 = make_float4(0.f, 0.f, 0.f, 0.f);
    float4 a1 = make_float4(0.f, 0.f, 0.f, 0.f);
    int j = beg;
    for (; j + 3 < end; j += 4) {
        int s0 = srcs[j], s1 = srcs[j + 1], s2 = srcs[j + 2], s3 = srcs[j + 3];
        const float4* r0 = (const float4*)(X + (size_t)s0 * D);
        const float4* r1 = (const float4*)(X + (size_t)s1 * D);
        const float4* r2 = (const float4*)(X + (size_t)s2 * D);
        const float4* r3 = (const float4*)(X + (size_t)s3 * D);
        float4 v0 = r0[lane], v1 = r1[lane], v2 = r2[lane], v3 = r3[lane];
        a0.x += (v0.x + v1.x) + (v2.x + v3.x);
        a0.y += (v0.y + v1.y) + (v2.y + v3.y);
        a0.z += (v0.z + v1.z) + (v2.z + v3.z);
        a0.w += (v0.w + v1.w) + (v2.w + v3.w);
        if (D == 256) {
            float4 u0 = r0[lane + 32], u1 = r1[lane + 32];
            float4 u2 = r2[lane + 32], u3 = r3[lane + 32];
            a1.x += (u0.x + u1.x) + (u2.x + u3.x);
            a1.y += (u0.y + u1.y) + (u2.y + u3.y);
            a1.z += (u0.z + u1.z) + (u2.z + u3.z);
            a1.w += (u0.w + u1.w) + (u2.w + u3.w);
        }
    }
    for (; j < end; j++) {
        int s = srcs[j];
        const float4* row = (const float4*)(X + (size_t)s * D);
        float4 v = row[lane];
        a0.x += v.x; a0.y += v.y; a0.z += v.z; a0.w += v.w;
        if (D == 256) {
            float4 u = row[lane + 32];
            a1.x += u.x; a1.y += u.y; a1.z += u.z; a1.w += u.w;
        }
    }
    int c = end - beg;
    float inv = 1.0f / (float)(c > 0 ? c : 1);
    float4* o = (float4*)(out + (size_t)g * D);
    o[lane] = make_float4(a0.x * inv, a0.y * inv, a0.z * inv, a0.w * inv);
    if (D == 256)
        o[lane + 32] = make_float4(a1.x * inv, a1.y * inv, a1.z * inv, a1.w * inv);
}

// ---------------- weight transpose + bf16 hi/lo split ----------------------
__device__ __forceinline__ void prep_one(const float* Wl, const float* Wr,
                                         int K1, int K, int N, int idx,
                                         __nv_bfloat16* hi, __nv_bfloat16* lo) {
    int n = idx / K, k = idx % K;
    float v = (k < K1) ? Wl[(size_t)k * N + n] : Wr[(size_t)(k - K1) * N + n];
    __nv_bfloat16 h = __float2bfloat16_rn(v);
    hi[(size_t)n * K + k] = h;
    lo[(size_t)n * K + k] = __float2bfloat16_rn(v - __bfloat162float(h));
}

__global__ void prep_all_kernel(const float* Wl0, const float* Wr0,
                                const float* Wl1, const float* Wr1,
                                const float* Wl2, const float* Wr2,
                                __nv_bfloat16* h0, __nv_bfloat16* l0,
                                __nv_bfloat16* h1, __nv_bfloat16* l1,
                                __nv_bfloat16* h2, __nv_bfloat16* l2) {
    int i = blockIdx.x * blockDim.x + threadIdx.x;
    const int S0 = 256 * 256, S1 = 256 * 512, S2 = 64 * 512;
    if (i < S0) prep_one(Wl0, Wr0, D_IN, 2 * D_IN, D_H, i, h0, l0);
    else if (i < S0 + S1) prep_one(Wl1, Wr1, D_H, 2 * D_H, D_H, i - S0, h1, l1);
    else if (i < S0 + S1 + S2) prep_one(Wl2, Wr2, D_H, 2 * D_H, D_OUT, i - S0 - S1, h2, l2);
}

// ----------------------- bf16x3 mma.sync SAGE GEMM -------------------------
template <int N, bool RELU>
__global__ void __launch_bounds__(256, 1)
sage_mma_gemm(const float* __restrict__ Aagg, int K1,
              const float* __restrict__ Adst, int ldDst, int K,
              const __nv_bfloat16* __restrict__ Wth,
              const __nv_bfloat16* __restrict__ Wtl,
              const float* __restrict__ bias, float* __restrict__ C,
              int rowOff) {
    extern __shared__ char smem[];
    constexpr int ASTR = 36;
    constexpr int BSTR = 40;
    constexpr int ABYTES = 128 * ASTR * 4;
    constexpr int BBYTES = N * BSTR * 2;
    constexpr int STAGE = ABYTES + 2 * BBYTES;
    const int tid = threadIdx.x;
    const int wid = tid >> 5;
    const int lane = tid & 31;
    const int g = lane >> 2;
    const int t = lane & 3;
    const int wm = (wid & 3) * 32;
    const int wn = (wid >> 2) * (N / 2);
    const int rowBase = rowOff + blockIdx.x * 128;
    const int NC = K / 32;
    constexpr int NIN = N / 16;

    const int q = lane >> 3;
    const uint32_t bLaneOff =
        (uint32_t)((wn + ((q & 2) << 2) + (lane & 7)) * (BSTR * 2) + (q & 1) * 16);

    float acc[2][NIN][4];
#pragma unroll
    for (int im = 0; im < 2; im++)
#pragma unroll
        for (int i = 0; i < NIN; i++)
#pragma unroll
            for (int qq = 0; qq < 4; qq++) acc[im][i][qq] = 0.f;

    auto issue_chunk = [&](int kc, int b) {
        char* stage = smem + b * STAGE;
        float* As = (float*)stage;
        __nv_bfloat16* Bh = (__nv_bfloat16*)(stage + ABYTES);
        __nv_bfloat16* Bl = (__nv_bfloat16*)(stage + ABYTES + BBYTES);
        const int acol = kc * 32;
        const bool inAgg = acol < K1;
        const float* abase = inAgg ? (Aagg + acol) : (Adst + (acol - K1));
        const int ald = inAgg ? K1 : ldDst;
#pragma unroll
        for (int p = 0; p < 4; p++) {
            int idx = p * 256 + tid;
            int r = idx >> 3, c4 = idx & 7;
            cp_async16(&As[r * ASTR + c4 * 4],
                       abase + (size_t)(rowBase + r) * ald + c4 * 4);
        }
#pragma unroll
        for (int p = 0; p < N / 64; p++) {
            int idx = p * 256 + tid;
            int r = idx >> 2, c8 = idx & 3;
            cp_async16(&Bh[r * BSTR + c8 * 8], Wth + (size_t)r * K + acol + c8 * 8);
            cp_async16(&Bl[r * BSTR + c8 * 8], Wtl + (size_t)r * K + acol + c8 * 8);
        }
        cp_async_commit();
    };

    issue_chunk(0, 0);
    if (NC > 1) issue_chunk(1, 1);

    for (int kc = 0; kc < NC; kc++) {
        const int b = kc % 3;
        __syncthreads();
        if (kc + 2 < NC) {
            issue_chunk(kc + 2, (kc + 2) % 3);
            cp_async_wait<2>();
        } else if (kc + 1 < NC) {
            cp_async_wait<1>();
        } else {
            cp_async_wait<0>();
        }
        __syncthreads();

        char* stage = smem + b * STAGE;
        const float* Ab = (const float*)stage;
        const uint32_t bhAddr =
            (uint32_t)__cvta_generic_to_shared(stage + ABYTES) + bLaneOff;
        const uint32_t blAddr = bhAddr + BBYTES;
#pragma unroll
        for (int s = 0; s < 2; s++) {
            const int kb = s * 16;
            uint32_t ah[2][4], al[2][4];
#pragma unroll
            for (int im = 0; im < 2; im++) {
                const int r0 = wm + im * 16 + g;
                float2 f0 = *(const float2*)&Ab[r0 * ASTR + kb + 2 * t];
                float2 f1 = *(const float2*)&Ab[(r0 + 8) * ASTR + kb + 2 * t];
                float2 f2 = *(const float2*)&Ab[r0 * ASTR + kb + 8 + 2 * t];
                float2 f3 = *(const float2*)&Ab[(r0 + 8) * ASTR + kb + 8 + 2 * t];
                split_bf16(f0, ah[im][0], al[im][0]);
                split_bf16(f1, ah[im][1], al[im][1]);
                split_bf16(f2, ah[im][2], al[im][2]);
                split_bf16(f3, ah[im][3], al[im][3]);
            }
#pragma unroll
            for (int i2 = 0; i2 < NIN / 2; i2++) {
                const uint32_t off = (uint32_t)(i2 * 16 * (BSTR * 2) + kb * 2);
                uint32_t bh[4], bl[4];
                ldmatrix_x4(bh[0], bh[1], bh[2], bh[3], bhAddr + off);
                ldmatrix_x4(bl[0], bl[1], bl[2], bl[3], blAddr + off);
                const uint32_t h0[2] = {bh[0], bh[1]};
                const uint32_t h1[2] = {bh[2], bh[3]};
                const uint32_t l0[2] = {bl[0], bl[1]};
                const uint32_t l1[2] = {bl[2], bl[3]};
                mma_bf16(acc[0][2 * i2], ah[0], h0);
                mma_bf16(acc[1][2 * i2], ah[1], h0);
                mma_bf16(acc[0][2 * i2], ah[0], l0);
                mma_bf16(acc[1][2 * i2], ah[1], l0);
                mma_bf16(acc[0][2 * i2], al[0], h0);
                mma_bf16(acc[1][2 * i2], al[1], h0);
                mma_bf16(acc[0][2 * i2 + 1], ah[0], h1);
                mma_bf16(acc[1][2 * i2 + 1], ah[1], h1);
                mma_bf16(acc[0][2 * i2 + 1], ah[0], l1);
                mma_bf16(acc[1][2 * i2 + 1], ah[1], l1);
                mma_bf16(acc[0][2 * i2 + 1], al[0], h1);
                mma_bf16(acc[1][2 * i2 + 1], al[1], h1);
            }
        }
    }

    // ---- epilogue ----
#pragma unroll
    for (int i = 0; i < NIN; i++) {
        const int col = wn + i * 8 + 2 * t;
        const float b0 = __ldg(bias + col);
        const float b1 = __ldg(bias + col + 1);
#pragma unroll
        for (int im = 0; im < 2; im++) {
            const int row = rowBase + wm + im * 16 + g;
            float v0 = acc[im][i][0] + b0;
            float v1 = acc[im][i][1] + b1;
            float v2 = acc[im][i][2] + b0;
            float v3 = acc[im][i][3] + b1;
            if (RELU) {
                v0 = fmaxf(v0, 0.f); v1 = fmaxf(v1, 0.f);
                v2 = fmaxf(v2, 0.f); v3 = fmaxf(v3, 0.f);
            }
            *(float2*)&C[(size_t)row * N + col] = make_float2(v0, v1);
            *(float2*)&C[(size_t)(row + 8) * N + col] = make_float2(v2, v3);
        }
    }
}

// ------------------------------- launcher ----------------------------------
static inline int cdiv(int a, int b) { return (a + b - 1) / b; }

extern "C" void kernel_launch(void* const* d_in, const int* in_sizes, int n_in,
                              void* d_out, int out_size) {
    const float* x   = (const float*)d_in[0];
    const float* Wl0 = (const float*)d_in[1];
    const float* bl0 = (const float*)d_in[2];
    const float* Wr0 = (const float*)d_in[3];
    const float* Wl1 = (const float*)d_in[4];
    const float* bl1 = (const float*)d_in[5];
    const float* Wr1 = (const float*)d_in[6];
    const float* Wl2 = (const float*)d_in[7];
    const float* bl2 = (const float*)d_in[8];
    const float* Wr2 = (const float*)d_in[9];
    const int* es0 = (const int*)d_in[10];
    const int* ed0 = (const int*)d_in[11];
    const int* es1 = (const int*)d_in[12];
    const int* ed1 = (const int*)d_in[13];
    const int* es2 = (const int*)d_in[14];
    const int* ed2 = (const int*)d_in[15];
    float* out = (float*)d_out;

    float *mean0, *h0, *mean1, *h1, *mean2;
    __nv_bfloat16 *wt0h, *wt0l, *wt1h, *wt1l, *wt2h, *wt2l;
    int *cnt0, *off0, *cur0, *esrc0;
    int *cnt1, *off1, *cur1, *esrc1;
    int *cnt2, *off2, *cur2, *esrc2;
    int *bsum;
    cudaGetSymbolAddress((void**)&mean0, g_mean0);
    cudaGetSymbolAddress((void**)&h0, g_h0);
    cudaGetSymbolAddress((void**)&mean1, g_mean1);
    cudaGetSymbolAddress((void**)&h1, g_h1);
    cudaGetSymbolAddress((void**)&mean2, g_mean2);
    cudaGetSymbolAddress((void**)&wt0h, g_wt0h);
    cudaGetSymbolAddress((void**)&wt0l, g_wt0l);
    cudaGetSymbolAddress((void**)&wt1h, g_wt1h);
    cudaGetSymbolAddress((void**)&wt1l, g_wt1l);
    cudaGetSymbolAddress((void**)&wt2h, g_wt2h);
    cudaGetSymbolAddress((void**)&wt2l, g_wt2l);
    cudaGetSymbolAddress((void**)&cnt0, g_cnt0);
    cudaGetSymbolAddress((void**)&off0, g_off0);
    cudaGetSymbolAddress((void**)&cur0, g_cur0);
    cudaGetSymbolAddress((void**)&esrc0, g_esrc0);
    cudaGetSymbolAddress((void**)&cnt1, g_cnt1);
    cudaGetSymbolAddress((void**)&off1, g_off1);
    cudaGetSymbolAddress((void**)&cur1, g_cur1);
    cudaGetSymbolAddress((void**)&esrc1, g_esrc1);
    cudaGetSymbolAddress((void**)&cnt2, g_cnt2);
    cudaGetSymbolAddress((void**)&off2, g_off2);
    cudaGetSymbolAddress((void**)&cur2, g_cur2);
    cudaGetSymbolAddress((void**)&esrc2, g_esrc2);
    cudaGetSymbolAddress((void**)&bsum, g_bsum);

    static cudaStream_t s2 = nullptr;
    static cudaEvent_t evStart, evA[L0_CHUNKS], evG, evCSR12;
    if (!s2) {
        cudaStreamCreateWithFlags(&s2, cudaStreamNonBlocking);
        cudaEventCreateWithFlags(&evStart, cudaEventDisableTiming);
        for (int i = 0; i < L0_CHUNKS; i++)
            cudaEventCreateWithFlags(&evA[i], cudaEventDisableTiming);
        cudaEventCreateWithFlags(&evG, cudaEventDisableTiming);
        cudaEventCreateWithFlags(&evCSR12, cudaEventDisableTiming);
    }

    constexpr int SMEM_256 = 3 * (128 * 36 * 4 + 2 * 256 * 40 * 2);  // 178176
    constexpr int SMEM_64  = 3 * (128 * 36 * 4 + 2 * 64 * 40 * 2);   // 86016
    cudaFuncSetAttribute(sage_mma_gemm<256, true>,
                         cudaFuncAttributeMaxDynamicSharedMemorySize, SMEM_256);
    cudaFuncSetAttribute(sage_mma_gemm<256, false>,
                         cudaFuncAttributeMaxDynamicSharedMemorySize, SMEM_256);
    cudaFuncSetAttribute(sage_mma_gemm<64, true>,
                         cudaFuncAttributeMaxDynamicSharedMemorySize, SMEM_64);

    // fork s2 from the capturing (main) stream
    cudaEventRecord(evStart, 0);
    cudaStreamWaitEvent(s2, evStart, 0);

    // ---- s2: weight prep + layers 1/2 CSR build (hidden under layer 0) ----
    prep_all_kernel<<<cdiv(256 * 256 + 256 * 512 + 64 * 512, 256), 256, 0, s2>>>(
        Wl0, Wr0, Wl1, Wr1, Wl2, Wr2, wt0h, wt0l, wt1h, wt1l, wt2h, wt2l);
    zero12_kernel<<<cdiv(N2 + N3, 256), 256, 0, s2>>>(cnt1, cnt2);
    hist_kernel<<<cdiv(E1, 256), 256, 0, s2>>>(ed1, E1, cnt1);
    hist_kernel<<<cdiv(E2, 256), 256, 0, s2>>>(ed2, E2, cnt2);
    exscan12_kernel<<<2, 1024, 0, s2>>>(cnt1, off1, cur1, cnt2, off2, cur2);
    scatter12_kernel<<<cdiv(E1 + E2, 256), 256, 0, s2>>>(
        es1, ed1, cur1, esrc1, es2, ed2, cur2, esrc2);
    cudaEventRecord(evCSR12, s2);

    // ---- main: layer-0 CSR build (scanB merged into scanC) ----
    zero0_kernel<<<cdiv(N1, 256), 256>>>(cnt0);
    hist_kernel<<<cdiv(E0, 256), 256>>>(ed0, E0, cnt0);
    scanA_kernel<<<NB0, 1024>>>(cnt0, N1, bsum);
    scanC_kernel<<<NB0, 1024>>>(cnt0, N1, E0, bsum, off0, cur0);
    scatter_kernel<<<cdiv(E0, 256), 256>>>(es0, ed0, E0, cur0, esrc0);

    // ---- layer 0: 8-chunk agg (main) / gemm (s2) pipeline ----
    for (int c = 0; c < L0_CHUNKS; c++) {
        aggregate_kernel<128><<<cdiv(L0_ROWS * 32, 256), 256>>>(
            x, off0, esrc0, mean0, L0_ROWS, c * L0_ROWS);
        cudaEventRecord(evA[c], 0);
        cudaStreamWaitEvent(s2, evA[c], 0);
        sage_mma_gemm<256, true><<<L0_TILES, 256, SMEM_256, s2>>>(
            mean0, D_IN, x, D_IN, 2 * D_IN, wt0h, wt0l, bl0, h0, c * L0_ROWS);
    }
    cudaEventRecord(evG, s2);
    cudaStreamWaitEvent(0, evG, 0);
    cudaStreamWaitEvent(0, evCSR12, 0);

    // ---- layer 1 (serial) ----
    aggregate_kernel<256><<<cdiv(N2 * 32, 256), 256>>>(h0, off1, esrc1, mean1, N2, 0);
    sage_mma_gemm<256, false><<<N2 / 128, 256, SMEM_256>>>(
        mean1, D_H, h0, D_H, 2 * D_H, wt1h, wt1l, bl1, h1, 0);

    // ---- layer 2 (serial) ----
    aggregate_kernel<256><<<cdiv(N3 * 32, 256), 256>>>(h1, off2, esrc2, mean2, N3, 0);
    sage_mma_gemm<64, true><<<N3 / 128, 256, SMEM_64>>>(
        mean2, D_H, h1, D_H, 2 * D_H, wt2h, wt2l, bl2, out, 0);
}